// round 9
// baseline (speedup 1.0000x reference)
#include <cuda_runtime.h>
#include <cuda_bf16.h>
#include <math.h>
#include <stdint.h>

// Problem constants
#define T_DIM 2048
#define C_DIM 1024
#define H_DIM 16
#define D_DIM 64
#define QKV_N (3 * C_DIM)   // 3072

// Scratch (allocation-free: __device__ globals)
__device__ float g_qkv[T_DIM * QKV_N];   // [T, 3C]
__device__ float g_y[T_DIM * C_DIM];     // [T, C] attention output

__device__ __forceinline__ uint32_t f2tf32(float x) {
    uint32_t r;
    asm("cvt.rna.tf32.f32 %0, %1;" : "=r"(r) : "f"(x));
    return r;
}

__device__ __forceinline__ void mma_tf32(float* d, const uint32_t* a, const uint32_t* b) {
    asm volatile(
        "mma.sync.aligned.m16n8k8.row.col.f32.tf32.tf32.f32 "
        "{%0,%1,%2,%3}, {%4,%5,%6,%7}, {%8,%9}, {%0,%1,%2,%3};"
        : "+f"(d[0]), "+f"(d[1]), "+f"(d[2]), "+f"(d[3])
        : "r"(a[0]), "r"(a[1]), "r"(a[2]), "r"(a[3]), "r"(b[0]), "r"(b[1]));
}

__device__ __forceinline__ uint32_t smem_u32(const void* p) {
    return (uint32_t)__cvta_generic_to_shared(p);
}
__device__ __forceinline__ void cp_async16(uint32_t dst, const void* src) {
    asm volatile("cp.async.cg.shared.global [%0], [%1], 16;" :: "r"(dst), "l"(src));
}
__device__ __forceinline__ void cp_commit() {
    asm volatile("cp.async.commit_group;");
}
template <int N>
__device__ __forceinline__ void cp_wait() {
    asm volatile("cp.async.wait_group %0;" :: "n"(N));
}

// ---------------------------------------------------------------------------
// TF32 tensor-core GEMM, double-buffered smem + register prefetch. (unchanged)
// C[M,N] = A[M,K] @ B[K,N] + bias[N]
// ---------------------------------------------------------------------------
#define GBM 128
#define GBN 128
#define GBK 32
#define AS_STRIDE 36
#define BS_STRIDE 136
#define AS_WORDS (GBM * AS_STRIDE)
#define BS_WORDS (GBK * BS_STRIDE)
#define GEMM_SMEM ((2 * AS_WORDS + 2 * BS_WORDS) * 4)

__global__ __launch_bounds__(256) void gemm_tf32_bias(
    int M, int N, int K,
    const float* __restrict__ A, const float* __restrict__ B,
    const float* __restrict__ bias, float* __restrict__ C)
{
    extern __shared__ uint32_t gsm[];
    uint32_t* AsBase = gsm;
    uint32_t* BsBase = gsm + 2 * AS_WORDS;

    const int tid  = threadIdx.x;
    const int lane = tid & 31;
    const int warp = tid >> 5;
    const int gid  = lane >> 2;
    const int tig  = lane & 3;

    const int wm = warp & 1;
    const int wn = warp >> 1;

    const int crow = blockIdx.y * GBM;
    const int ccol = blockIdx.x * GBN;

    const int arow  = tid >> 3;
    const int acol4 = tid & 7;
    const int brow32 = tid >> 5;
    const int bcol4  = tid & 31;

    float acc[4][4][4];
    #pragma unroll
    for (int i = 0; i < 4; i++)
        #pragma unroll
        for (int j = 0; j < 4; j++)
            #pragma unroll
            for (int r = 0; r < 4; r++) acc[i][j][r] = 0.0f;

    float4 aR[4], bR[4];

    #pragma unroll
    for (int p = 0; p < 4; p++) {
        aR[p] = *reinterpret_cast<const float4*>(
            &A[(size_t)(crow + arow + p * 32) * K + acol4 * 4]);
        bR[p] = *reinterpret_cast<const float4*>(
            &B[(size_t)(brow32 + p * 8) * N + ccol + bcol4 * 4]);
    }
    {
        uint32_t* As = AsBase;
        uint32_t* Bs = BsBase;
        #pragma unroll
        for (int p = 0; p < 4; p++) {
            uint32_t* da = &As[(arow + p * 32) * AS_STRIDE + acol4 * 4];
            da[0] = f2tf32(aR[p].x); da[1] = f2tf32(aR[p].y);
            da[2] = f2tf32(aR[p].z); da[3] = f2tf32(aR[p].w);
            uint32_t* db = &Bs[(brow32 + p * 8) * BS_STRIDE + bcol4 * 4];
            db[0] = f2tf32(bR[p].x); db[1] = f2tf32(bR[p].y);
            db[2] = f2tf32(bR[p].z); db[3] = f2tf32(bR[p].w);
        }
    }
    __syncthreads();

    int buf = 0;
    for (int k0 = 0; k0 < K; k0 += GBK) {
        const bool has_next = (k0 + GBK < K);
        if (has_next) {
            const int kn = k0 + GBK;
            #pragma unroll
            for (int p = 0; p < 4; p++) {
                aR[p] = *reinterpret_cast<const float4*>(
                    &A[(size_t)(crow + arow + p * 32) * K + kn + acol4 * 4]);
                bR[p] = *reinterpret_cast<const float4*>(
                    &B[(size_t)(kn + brow32 + p * 8) * N + ccol + bcol4 * 4]);
            }
        }

        uint32_t* As = AsBase + buf * AS_WORDS;
        uint32_t* Bs = BsBase + buf * BS_WORDS;
        #pragma unroll
        for (int kk = 0; kk < 4; kk++) {
            const int kb = kk * 8;
            uint32_t af[4][4], bf[4][2];
            #pragma unroll
            for (int mi = 0; mi < 4; mi++) {
                const int m = wm * 64 + mi * 16 + gid;
                af[mi][0] = As[(m    ) * AS_STRIDE + kb + tig    ];
                af[mi][1] = As[(m + 8) * AS_STRIDE + kb + tig    ];
                af[mi][2] = As[(m    ) * AS_STRIDE + kb + tig + 4];
                af[mi][3] = As[(m + 8) * AS_STRIDE + kb + tig + 4];
            }
            #pragma unroll
            for (int ni = 0; ni < 4; ni++) {
                const int n = wn * 32 + ni * 8 + gid;
                bf[ni][0] = Bs[(kb + tig    ) * BS_STRIDE + n];
                bf[ni][1] = Bs[(kb + tig + 4) * BS_STRIDE + n];
            }
            #pragma unroll
            for (int mi = 0; mi < 4; mi++)
                #pragma unroll
                for (int ni = 0; ni < 4; ni++)
                    mma_tf32(acc[mi][ni], af[mi], bf[ni]);
        }

        if (has_next) {
            uint32_t* Asn = AsBase + (buf ^ 1) * AS_WORDS;
            uint32_t* Bsn = BsBase + (buf ^ 1) * BS_WORDS;
            #pragma unroll
            for (int p = 0; p < 4; p++) {
                uint32_t* da = &Asn[(arow + p * 32) * AS_STRIDE + acol4 * 4];
                da[0] = f2tf32(aR[p].x); da[1] = f2tf32(aR[p].y);
                da[2] = f2tf32(aR[p].z); da[3] = f2tf32(aR[p].w);
                uint32_t* db = &Bsn[(brow32 + p * 8) * BS_STRIDE + bcol4 * 4];
                db[0] = f2tf32(bR[p].x); db[1] = f2tf32(bR[p].y);
                db[2] = f2tf32(bR[p].z); db[3] = f2tf32(bR[p].w);
            }
            __syncthreads();
            buf ^= 1;
        }
    }

    #pragma unroll
    for (int mi = 0; mi < 4; mi++) {
        const int r = crow + wm * 64 + mi * 16 + gid;
        #pragma unroll
        for (int ni = 0; ni < 4; ni++) {
            const int c = ccol + wn * 32 + ni * 8 + 2 * tig;
            const float b0 = bias[c], b1 = bias[c + 1];
            float2 o1 = make_float2(acc[mi][ni][0] + b0, acc[mi][ni][1] + b1);
            float2 o2 = make_float2(acc[mi][ni][2] + b0, acc[mi][ni][3] + b1);
            *reinterpret_cast<float2*>(&C[(size_t)r * N + c]) = o1;
            *reinterpret_cast<float2*>(&C[(size_t)(r + 8) * N + c]) = o2;
        }
    }
}

// ---------------------------------------------------------------------------
// Fast exp on FMA/ALU pipes only. Valid for x <= 0 (clamped). Rel err ~2e-6.
// ---------------------------------------------------------------------------
__device__ __forceinline__ float fast_exp(float x) {
    x = fmaxf(x, -87.3f);
    float z = x * 1.4426950408889634f;
    float t = z + 12582912.0f;
    int   n = __float_as_int(t);
    float fi = t - 12582912.0f;
    float f = z - fi;
    float p =          1.3534543e-3f;
    p = fmaf(p, f,     9.6178720e-3f);
    p = fmaf(p, f,     5.5503429e-2f);
    p = fmaf(p, f,     2.4022651e-1f);
    p = fmaf(p, f,     6.9314718e-1f);
    p = fmaf(p, f,     1.0f);
    int sb = (n << 23) + 0x3F800000;
    return p * __int_as_float(sb);
}

// ---------------------------------------------------------------------------
// Tensor-core flash attention, warp-per-16-rows decomposition.
// 8 warps x 16 query rows; each warp computes ALL 64 key cols, so the online
// softmax is warp-local (tig-group shfls, no smem) and the QK C-fragment ->
// PV A-fragment conversion is done with in-warp shfls (P never hits smem).
// K/V staged raw via cp.async double buffer; tf32 cvt at fragment load.
// 2 barriers per iteration. Smem 70KB -> 2 CTAs/SM -> grid fits in one wave.
// ---------------------------------------------------------------------------
#define FA_M 128
#define FA_S 64
#define KSTR 68
#define VSTR 72
#define KT_WORDS (FA_S * KSTR)   // 4352
#define VT_WORDS (FA_S * VSTR)   // 4608
#define ATTN_SMEM ((2 * KT_WORDS + 2 * VT_WORDS) * 4)   // 71680 B

__global__ __launch_bounds__(256) void attn_tc(
    const float* __restrict__ qkv, float* __restrict__ y)
{
    extern __shared__ float sm[];
    float* Kbuf = sm;                      // 2 x [64][KSTR]; also Q staging (128*68)
    float* Vbuf = sm + 2 * KT_WORDS;       // 2 x [64][VSTR]

    const int h  = blockIdx.y;
    const int q0 = blockIdx.x * FA_M;
    const int tid  = threadIdx.x;
    const int lane = tid & 31;
    const int warp = tid >> 5;
    const int g    = lane >> 2;   // group id 0..7
    const int t    = lane & 3;    // thread in group 0..3
    const int m    = warp * 16 + g;   // this thread's first query row (and m+8)

    const float* qbase = qkv + h * D_DIM;
    const float* kbase = qkv + C_DIM + h * D_DIM;
    const float* vbase = qkv + 2 * C_DIM + h * D_DIM;

    // ---- stage Q tile (tf32, pre-scaled 1/8) into Kbuf area, stride 68 ----
    for (int i = tid; i < FA_M * 16; i += 256) {
        const int r  = i >> 4;
        const int c4 = i & 15;
        float4 v = *reinterpret_cast<const float4*>(
            &qbase[(size_t)(q0 + r) * QKV_N + c4 * 4]);
        float* dst = &Kbuf[r * KSTR + c4 * 4];
        dst[0] = __int_as_float(f2tf32(v.x * 0.125f));
        dst[1] = __int_as_float(f2tf32(v.y * 0.125f));
        dst[2] = __int_as_float(f2tf32(v.z * 0.125f));
        dst[3] = __int_as_float(f2tf32(v.w * 0.125f));
    }
    __syncthreads();

    // ---- persistent Q fragments (16 rows x 64 k) ----
    uint32_t qf[8][4];
    #pragma unroll
    for (int kk = 0; kk < 8; kk++) {
        const int kb = kk * 8;
        qf[kk][0] = __float_as_uint(Kbuf[(m    ) * KSTR + kb + t    ]);
        qf[kk][1] = __float_as_uint(Kbuf[(m + 8) * KSTR + kb + t    ]);
        qf[kk][2] = __float_as_uint(Kbuf[(m    ) * KSTR + kb + t + 4]);
        qf[kk][3] = __float_as_uint(Kbuf[(m + 8) * KSTR + kb + t + 4]);
    }
    __syncthreads();   // Q reads done before K staging overwrites Kbuf

    // ---- prologue: async-stage K/V tile 0 into buffer 0 ----
    #pragma unroll
    for (int p = 0; p < 4; p++) {
        const int idx = tid + p * 256;
        const int r  = idx >> 4;
        const int c4 = idx & 15;
        cp_async16(smem_u32(&Kbuf[r * KSTR + c4 * 4]),
                   &kbase[(size_t)r * QKV_N + c4 * 4]);
        cp_async16(smem_u32(&Vbuf[r * VSTR + c4 * 4]),
                   &vbase[(size_t)r * QKV_N + c4 * 4]);
    }
    cp_commit();

    float oacc[8][4];
    #pragma unroll
    for (int ni = 0; ni < 8; ni++)
        #pragma unroll
        for (int r = 0; r < 4; r++) oacc[ni][r] = 0.0f;

    float mrun0 = -1e30f, mrun1 = -1e30f;
    float lrun0 = 0.0f,   lrun1 = 0.0f;

    const int srcA = (lane & 28) | (t >> 1);   // 4*g + (t>>1)
    const int srcB = srcA + 2;

    int buf = 0;
    for (int it = 0; it < T_DIM / FA_S; it++) {
        const bool has_next = (it + 1 < T_DIM / FA_S);
        if (has_next) {
            const int s0n = (it + 1) * FA_S;
            float* Kn = Kbuf + (buf ^ 1) * KT_WORDS;
            float* Vn = Vbuf + (buf ^ 1) * VT_WORDS;
            #pragma unroll
            for (int p = 0; p < 4; p++) {
                const int idx = tid + p * 256;
                const int r  = idx >> 4;
                const int c4 = idx & 15;
                cp_async16(smem_u32(&Kn[r * KSTR + c4 * 4]),
                           &kbase[(size_t)(s0n + r) * QKV_N + c4 * 4]);
                cp_async16(smem_u32(&Vn[r * VSTR + c4 * 4]),
                           &vbase[(size_t)(s0n + r) * QKV_N + c4 * 4]);
            }
            cp_commit();
            cp_wait<1>();
        } else {
            cp_wait<0>();
        }
        __syncthreads();   // current tile visible everywhere

        const float* Ks = Kbuf + buf * KT_WORDS;
        const float* Vs = Vbuf + buf * VT_WORDS;

        // ---- S = Q @ K^T : 16 rows x 64 keys per warp ----
        float sacc[8][4];
        #pragma unroll
        for (int ni = 0; ni < 8; ni++)
            #pragma unroll
            for (int r = 0; r < 4; r++) sacc[ni][r] = 0.0f;

        #pragma unroll
        for (int kk = 0; kk < 8; kk++) {
            const int kb = kk * 8;
            #pragma unroll
            for (int ni = 0; ni < 8; ni++) {
                const int n = ni * 8 + g;   // key row
                uint32_t bf[2];
                bf[0] = f2tf32(Ks[n * KSTR + kb + t    ]);
                bf[1] = f2tf32(Ks[n * KSTR + kb + t + 4]);
                mma_tf32(sacc[ni], qf[kk], bf);
            }
        }

        // ---- warp-local online softmax (rows m and m+8) ----
        float px0 = -1e30f, px1 = -1e30f;
        #pragma unroll
        for (int ni = 0; ni < 8; ni++) {
            px0 = fmaxf(px0, fmaxf(sacc[ni][0], sacc[ni][1]));
            px1 = fmaxf(px1, fmaxf(sacc[ni][2], sacc[ni][3]));
        }
        px0 = fmaxf(px0, __shfl_xor_sync(0xffffffff, px0, 1));
        px0 = fmaxf(px0, __shfl_xor_sync(0xffffffff, px0, 2));
        px1 = fmaxf(px1, __shfl_xor_sync(0xffffffff, px1, 1));
        px1 = fmaxf(px1, __shfl_xor_sync(0xffffffff, px1, 2));

        const float mnew0 = fmaxf(mrun0, px0);
        const float mnew1 = fmaxf(mrun1, px1);
        const float corr0 = fast_exp(mrun0 - mnew0);
        const float corr1 = fast_exp(mrun1 - mnew1);
        mrun0 = mnew0; mrun1 = mnew1;
        lrun0 *= corr0; lrun1 *= corr1;

        float ps0 = 0.0f, ps1 = 0.0f;
        #pragma unroll
        for (int ni = 0; ni < 8; ni++) {
            float p0 = fast_exp(sacc[ni][0] - mnew0);
            float p1 = fast_exp(sacc[ni][1] - mnew0);
            float p2 = fast_exp(sacc[ni][2] - mnew1);
            float p3 = fast_exp(sacc[ni][3] - mnew1);
            ps0 += p0 + p1;
            ps1 += p2 + p3;
            sacc[ni][0] = __int_as_float(f2tf32(p0));
            sacc[ni][1] = __int_as_float(f2tf32(p1));
            sacc[ni][2] = __int_as_float(f2tf32(p2));
            sacc[ni][3] = __int_as_float(f2tf32(p3));
            oacc[ni][0] *= corr0; oacc[ni][1] *= corr0;
            oacc[ni][2] *= corr1; oacc[ni][3] *= corr1;
        }
        ps0 += __shfl_xor_sync(0xffffffff, ps0, 1);
        ps0 += __shfl_xor_sync(0xffffffff, ps0, 2);
        ps1 += __shfl_xor_sync(0xffffffff, ps1, 1);
        ps1 += __shfl_xor_sync(0xffffffff, ps1, 2);
        lrun0 += ps0;
        lrun1 += ps1;

        // ---- O += P @ V ; P C-frags -> A-frags via in-warp shfl ----
        #pragma unroll
        for (int kk = 0; kk < 8; kk++) {
            // P block kk (cols kk*8..kk*8+7) is the A operand for k-chunk kk
            const uint32_t c0 = __float_as_uint(sacc[kk][0]);
            const uint32_t c1 = __float_as_uint(sacc[kk][1]);
            const uint32_t c2 = __float_as_uint(sacc[kk][2]);
            const uint32_t c3 = __float_as_uint(sacc[kk][3]);
            const uint32_t x0 = __shfl_sync(0xffffffff, c0, srcA);
            const uint32_t x1 = __shfl_sync(0xffffffff, c1, srcA);
            const uint32_t x2 = __shfl_sync(0xffffffff, c2, srcA);
            const uint32_t x3 = __shfl_sync(0xffffffff, c3, srcA);
            const uint32_t y0 = __shfl_sync(0xffffffff, c0, srcB);
            const uint32_t y1 = __shfl_sync(0xffffffff, c1, srcB);
            const uint32_t y2 = __shfl_sync(0xffffffff, c2, srcB);
            const uint32_t y3 = __shfl_sync(0xffffffff, c3, srcB);
            uint32_t af[4];
            af[0] = (t & 1) ? x1 : x0;
            af[1] = (t & 1) ? x3 : x2;
            af[2] = (t & 1) ? y1 : y0;
            af[3] = (t & 1) ? y3 : y2;

            const int kb = kk * 8;
            #pragma unroll
            for (int ni = 0; ni < 8; ni++) {
                const int n = ni * 8 + g;   // d-col
                uint32_t bf[2];
                bf[0] = f2tf32(Vs[(kb + t    ) * VSTR + n]);
                bf[1] = f2tf32(Vs[(kb + t + 4) * VSTR + n]);
                mma_tf32(oacc[ni], af, bf);
            }
        }
        __syncthreads();   // all reads of current buffers done before overwrite
        buf ^= 1;
    }

    // ---- epilogue: normalize, store ----
    const float il0 = 1.0f / lrun0;
    const float il1 = 1.0f / lrun1;
    float* y1p = y + (size_t)(q0 + m) * C_DIM + h * D_DIM;
    float* y2p = y + (size_t)(q0 + m + 8) * C_DIM + h * D_DIM;
    #pragma unroll
    for (int ni = 0; ni < 8; ni++) {
        const int c = ni * 8 + 2 * t;
        *reinterpret_cast<float2*>(y1p + c) =
            make_float2(oacc[ni][0] * il0, oacc[ni][1] * il0);
        *reinterpret_cast<float2*>(y2p + c) =
            make_float2(oacc[ni][2] * il1, oacc[ni][3] * il1);
    }
}

// ---------------------------------------------------------------------------
// kernel_launch
// ---------------------------------------------------------------------------
extern "C" void kernel_launch(void* const* d_in, const int* in_sizes, int n_in,
                              void* d_out, int out_size)
{
    const float* x      = (const float*)d_in[0];
    const float* W_qkv  = (const float*)d_in[1];
    const float* b_qkv  = (const float*)d_in[2];
    const float* W_proj = (const float*)d_in[3];
    const float* b_proj = (const float*)d_in[4];
    float* out = (float*)d_out;

    float *qkv, *y;
    cudaGetSymbolAddress((void**)&qkv, g_qkv);
    cudaGetSymbolAddress((void**)&y, g_y);

    cudaFuncSetAttribute(gemm_tf32_bias,
        cudaFuncAttributeMaxDynamicSharedMemorySize, GEMM_SMEM);
    cudaFuncSetAttribute(attn_tc,
        cudaFuncAttributeMaxDynamicSharedMemorySize, ATTN_SMEM);

    gemm_tf32_bias<<<dim3(QKV_N / GBN, T_DIM / GBM), 256, GEMM_SMEM>>>(
        T_DIM, QKV_N, C_DIM, x, W_qkv, b_qkv, qkv);

    attn_tc<<<dim3(T_DIM / FA_M, H_DIM), 256, ATTN_SMEM>>>(qkv, y);

    gemm_tf32_bias<<<dim3(C_DIM / GBN, T_DIM / GBM), 256, GEMM_SMEM>>>(
        T_DIM, C_DIM, C_DIM, y, W_proj, b_proj, out);
}

// round 10
// speedup vs baseline: 1.1092x; 1.1092x over previous
#include <cuda_runtime.h>
#include <cuda_bf16.h>
#include <math.h>
#include <stdint.h>

// Problem constants
#define T_DIM 2048
#define C_DIM 1024
#define H_DIM 16
#define D_DIM 64
#define QKV_N (3 * C_DIM)   // 3072

// Scratch (allocation-free: __device__ globals)
__device__ float g_qkv[T_DIM * QKV_N];    // [T, 3C] tf32-rounded qkv
__device__ float g_y[T_DIM * C_DIM];      // [T, C] tf32-rounded attention out
__device__ float g_xr[T_DIM * C_DIM];     // tf32-rounded x
__device__ float g_wqr[C_DIM * QKV_N];    // tf32-rounded W_qkv
__device__ float g_wpr[C_DIM * C_DIM];    // tf32-rounded W_proj

__device__ __forceinline__ uint32_t f2tf32(float x) {
    uint32_t r;
    asm("cvt.rna.tf32.f32 %0, %1;" : "=r"(r) : "f"(x));
    return r;
}

__device__ __forceinline__ void mma_tf32(float* d, const uint32_t* a, const uint32_t* b) {
    asm volatile(
        "mma.sync.aligned.m16n8k8.row.col.f32.tf32.tf32.f32 "
        "{%0,%1,%2,%3}, {%4,%5,%6,%7}, {%8,%9}, {%0,%1,%2,%3};"
        : "+f"(d[0]), "+f"(d[1]), "+f"(d[2]), "+f"(d[3])
        : "r"(a[0]), "r"(a[1]), "r"(a[2]), "r"(a[3]), "r"(b[0]), "r"(b[1]));
}

__device__ __forceinline__ uint32_t smem_u32(const void* p) {
    return (uint32_t)__cvta_generic_to_shared(p);
}
__device__ __forceinline__ void cp_async16(uint32_t dst, const void* src) {
    asm volatile("cp.async.cg.shared.global [%0], [%1], 16;" :: "r"(dst), "l"(src));
}
__device__ __forceinline__ void cp_commit() {
    asm volatile("cp.async.commit_group;");
}
template <int N>
__device__ __forceinline__ void cp_wait() {
    asm volatile("cp.async.wait_group %0;" :: "n"(N));
}

// ---------------------------------------------------------------------------
// Elementwise tf32 RNA pre-round (hoisted out of all GEMM/attention loops)
// ---------------------------------------------------------------------------
__global__ void round_tf32_kernel(const float4* __restrict__ in,
                                  float4* __restrict__ out, int n4)
{
    const int i = blockIdx.x * blockDim.x + threadIdx.x;
    if (i < n4) {
        float4 v = in[i];
        float4 o;
        o.x = __int_as_float(f2tf32(v.x));
        o.y = __int_as_float(f2tf32(v.y));
        o.z = __int_as_float(f2tf32(v.z));
        o.w = __int_as_float(f2tf32(v.w));
        out[i] = o;
    }
}

// ---------------------------------------------------------------------------
// TF32 tensor-core GEMM, cp.async 3-stage pipeline, zero cvts.
// Inputs A,B must be pre-rounded to tf32 values. C = A@B + bias.
// round_out != 0 -> store tf32-rounded result (for downstream consumers).
// ---------------------------------------------------------------------------
#define GBM 128
#define GBN 128
#define GBK 32
#define AS_STRIDE 36
#define BS_STRIDE 136
#define AS_WORDS (GBM * AS_STRIDE)            // 4608
#define BS_WORDS (GBK * BS_STRIDE)            // 4352
#define STAGE_WORDS (AS_WORDS + BS_WORDS)     // 8960
#define GSTAGES 3
#define GEMM_SMEM (GSTAGES * STAGE_WORDS * 4) // 107520 B

__global__ __launch_bounds__(256) void gemm_tf32_bias(
    int M, int N, int K,
    const float* __restrict__ A, const float* __restrict__ B,
    const float* __restrict__ bias, float* __restrict__ C, int round_out)
{
    extern __shared__ uint32_t gsm[];

    const int tid  = threadIdx.x;
    const int lane = tid & 31;
    const int warp = tid >> 5;
    const int gid  = lane >> 2;
    const int tig  = lane & 3;

    const int wm = warp & 1;
    const int wn = warp >> 1;

    const int crow = blockIdx.y * GBM;
    const int ccol = blockIdx.x * GBN;

    const int niter = K / GBK;

    // stage one K-tile (A 128x32, B 32x128) via 2048 16B cp.async chunks
    auto stage = [&](int s, int k0) {
        uint32_t* As = gsm + s * STAGE_WORDS;
        uint32_t* Bs = As + AS_WORDS;
        #pragma unroll
        for (int p = 0; p < 4; p++) {
            const int idx = tid + p * 256;       // 0..1023
            const int ra  = idx >> 3;            // 0..127
            const int ca  = idx & 7;             // 0..7
            cp_async16(smem_u32(&As[ra * AS_STRIDE + ca * 4]),
                       &A[(size_t)(crow + ra) * K + k0 + ca * 4]);
            const int rb  = idx >> 5;            // 0..31
            const int cb  = idx & 31;            // 0..31
            cp_async16(smem_u32(&Bs[rb * BS_STRIDE + cb * 4]),
                       &B[(size_t)(k0 + rb) * N + ccol + cb * 4]);
        }
    };

    float acc[4][4][4];
    #pragma unroll
    for (int i = 0; i < 4; i++)
        #pragma unroll
        for (int j = 0; j < 4; j++)
            #pragma unroll
            for (int r = 0; r < 4; r++) acc[i][j][r] = 0.0f;

    // prologue: stage tiles 0 and 1
    stage(0, 0);       cp_commit();
    stage(1, GBK);     cp_commit();

    for (int i = 0; i < niter; i++) {
        if (i == niter - 1) { cp_wait<0>(); } else { cp_wait<1>(); }
        __syncthreads();

        const uint32_t* As = gsm + (i % GSTAGES) * STAGE_WORDS;
        const uint32_t* Bs = As + AS_WORDS;

        #pragma unroll
        for (int kk = 0; kk < 4; kk++) {
            const int kb = kk * 8;
            uint32_t af[4][4], bf[4][2];
            #pragma unroll
            for (int mi = 0; mi < 4; mi++) {
                const int m = wm * 64 + mi * 16 + gid;
                af[mi][0] = As[(m    ) * AS_STRIDE + kb + tig    ];
                af[mi][1] = As[(m + 8) * AS_STRIDE + kb + tig    ];
                af[mi][2] = As[(m    ) * AS_STRIDE + kb + tig + 4];
                af[mi][3] = As[(m + 8) * AS_STRIDE + kb + tig + 4];
            }
            #pragma unroll
            for (int ni = 0; ni < 4; ni++) {
                const int n = wn * 32 + ni * 8 + gid;
                bf[ni][0] = Bs[(kb + tig    ) * BS_STRIDE + n];
                bf[ni][1] = Bs[(kb + tig + 4) * BS_STRIDE + n];
            }
            #pragma unroll
            for (int mi = 0; mi < 4; mi++)
                #pragma unroll
                for (int ni = 0; ni < 4; ni++)
                    mma_tf32(acc[mi][ni], af[mi], bf[ni]);
        }

        if (i + 2 < niter) {
            stage((i + 2) % GSTAGES, (i + 2) * GBK);
            cp_commit();
        }
    }

    #pragma unroll
    for (int mi = 0; mi < 4; mi++) {
        const int r = crow + wm * 64 + mi * 16 + gid;
        #pragma unroll
        for (int ni = 0; ni < 4; ni++) {
            const int c = ccol + wn * 32 + ni * 8 + 2 * tig;
            const float b0 = bias[c], b1 = bias[c + 1];
            float o0 = acc[mi][ni][0] + b0, o1 = acc[mi][ni][1] + b1;
            float o2 = acc[mi][ni][2] + b0, o3 = acc[mi][ni][3] + b1;
            if (round_out) {
                o0 = __int_as_float(f2tf32(o0));
                o1 = __int_as_float(f2tf32(o1));
                o2 = __int_as_float(f2tf32(o2));
                o3 = __int_as_float(f2tf32(o3));
            }
            *reinterpret_cast<float2*>(&C[(size_t)r * N + c]) =
                make_float2(o0, o1);
            *reinterpret_cast<float2*>(&C[(size_t)(r + 8) * N + c]) =
                make_float2(o2, o3);
        }
    }
}

// ---------------------------------------------------------------------------
// Fast exp on FMA/ALU pipes only. Valid for x <= 0 (clamped). Rel err ~2e-6.
// ---------------------------------------------------------------------------
__device__ __forceinline__ float fast_exp(float x) {
    x = fmaxf(x, -87.3f);
    float z = x * 1.4426950408889634f;
    float t = z + 12582912.0f;
    int   n = __float_as_int(t);
    float fi = t - 12582912.0f;
    float f = z - fi;
    float p =          1.3534543e-3f;
    p = fmaf(p, f,     9.6178720e-3f);
    p = fmaf(p, f,     5.5503429e-2f);
    p = fmaf(p, f,     2.4022651e-1f);
    p = fmaf(p, f,     6.9314718e-1f);
    p = fmaf(p, f,     1.0f);
    int sb = (n << 23) + 0x3F800000;
    return p * __int_as_float(sb);
}

// ---------------------------------------------------------------------------
// Tensor-core flash attention (R8 structure: 4(m) x 2(n) warps), but qkv is
// PRE-ROUNDED tf32 -> zero cvts in the mainloop. cp.async double-buffered
// K/V staging; V consumed in natural [s][d] layout.
// ---------------------------------------------------------------------------
#define FA_M 128
#define FA_S 64
#define SSTR 68
#define KSTR 68
#define VSTR 72
#define KT_WORDS (FA_S * KSTR)   // 4352
#define VT_WORDS (FA_S * VSTR)   // 4608
#define ATTN_SMEM ((128 * SSTR + 2 * KT_WORDS + 2 * VT_WORDS + 2 * 128 + 2 * 128) * 4)

__global__ __launch_bounds__(256) void attn_tc(
    const float* __restrict__ qkv, float* __restrict__ y)
{
    extern __shared__ float sm[];
    float* S     = sm;                         // [128][SSTR]  (Q staging, then P)
    float* Kbuf  = sm + 128 * SSTR;            // 2 x [64][KSTR]
    float* Vbuf  = Kbuf + 2 * KT_WORDS;        // 2 x [64][VSTR]
    float* Pmx   = Vbuf + 2 * VT_WORDS;        // [128][2]
    float* Psm   = Pmx + 2 * 128;              // [128][2]

    const int h  = blockIdx.y;
    const int q0 = blockIdx.x * FA_M;
    const int tid  = threadIdx.x;
    const int lane = tid & 31;
    const int warp = tid >> 5;
    const int gid  = lane >> 2;
    const int tig  = lane & 3;
    const int wm   = warp & 3;    // 0..3 -> 32 m-rows each
    const int wn   = warp >> 2;   // 0..1 -> 32 n-cols each

    const float* qbase = qkv + h * D_DIM;
    const float* kbase = qkv + C_DIM + h * D_DIM;
    const float* vbase = qkv + 2 * C_DIM + h * D_DIM;

    // ---- stage Q tile into S; qkv pre-rounded, *0.125 is exact ----
    for (int i = tid; i < FA_M * 16; i += 256) {
        const int r  = i >> 4;
        const int c4 = i & 15;
        float4 v = *reinterpret_cast<const float4*>(
            &qbase[(size_t)(q0 + r) * QKV_N + c4 * 4]);
        float* dst = &S[r * SSTR + c4 * 4];
        dst[0] = v.x * 0.125f;
        dst[1] = v.y * 0.125f;
        dst[2] = v.z * 0.125f;
        dst[3] = v.w * 0.125f;
    }

    // ---- prologue: async-stage K/V tile 0 into buffer 0 ----
    #pragma unroll
    for (int p = 0; p < 4; p++) {
        const int idx = tid + p * 256;
        const int r  = idx >> 4;
        const int c4 = idx & 15;
        cp_async16(smem_u32(&Kbuf[r * KSTR + c4 * 4]),
                   &kbase[(size_t)r * QKV_N + c4 * 4]);
        cp_async16(smem_u32(&Vbuf[r * VSTR + c4 * 4]),
                   &vbase[(size_t)r * QKV_N + c4 * 4]);
    }
    cp_commit();
    __syncthreads();   // Q visible

    // ---- load persistent Q fragments (no cvt: pre-rounded) ----
    uint32_t qf[2][8][4];
    #pragma unroll
    for (int mi = 0; mi < 2; mi++) {
        const int m = wm * 32 + mi * 16 + gid;
        #pragma unroll
        for (int kk = 0; kk < 8; kk++) {
            const int kb = kk * 8;
            qf[mi][kk][0] = __float_as_uint(S[(m    ) * SSTR + kb + tig    ]);
            qf[mi][kk][1] = __float_as_uint(S[(m + 8) * SSTR + kb + tig    ]);
            qf[mi][kk][2] = __float_as_uint(S[(m    ) * SSTR + kb + tig + 4]);
            qf[mi][kk][3] = __float_as_uint(S[(m + 8) * SSTR + kb + tig + 4]);
        }
    }

    float oacc[2][4][4];
    #pragma unroll
    for (int mi = 0; mi < 2; mi++)
        #pragma unroll
        for (int ni = 0; ni < 4; ni++)
            #pragma unroll
            for (int r = 0; r < 4; r++) oacc[mi][ni][r] = 0.0f;

    float mrun[4] = {-1e30f, -1e30f, -1e30f, -1e30f};
    float lrun[4] = {0.0f, 0.0f, 0.0f, 0.0f};

    int buf = 0;
    for (int it = 0; it < T_DIM / FA_S; it++) {
        const bool has_next = (it + 1 < T_DIM / FA_S);
        if (has_next) {
            const int s0n = (it + 1) * FA_S;
            float* Kn = Kbuf + (buf ^ 1) * KT_WORDS;
            float* Vn = Vbuf + (buf ^ 1) * VT_WORDS;
            #pragma unroll
            for (int p = 0; p < 4; p++) {
                const int idx = tid + p * 256;
                const int r  = idx >> 4;
                const int c4 = idx & 15;
                cp_async16(smem_u32(&Kn[r * KSTR + c4 * 4]),
                           &kbase[(size_t)(s0n + r) * QKV_N + c4 * 4]);
                cp_async16(smem_u32(&Vn[r * VSTR + c4 * 4]),
                           &vbase[(size_t)(s0n + r) * QKV_N + c4 * 4]);
            }
            cp_commit();
            cp_wait<1>();
        } else {
            cp_wait<0>();
        }
        __syncthreads();

        const float* Ks = Kbuf + buf * KT_WORDS;
        const float* Vs = Vbuf + buf * VT_WORDS;

        // ---- S = Q @ K^T ----
        float sacc[2][4][4];
        #pragma unroll
        for (int mi = 0; mi < 2; mi++)
            #pragma unroll
            for (int ni = 0; ni < 4; ni++)
                #pragma unroll
                for (int r = 0; r < 4; r++) sacc[mi][ni][r] = 0.0f;

        #pragma unroll
        for (int kk = 0; kk < 8; kk++) {
            const int kb = kk * 8;
            uint32_t bf[4][2];
            #pragma unroll
            for (int ni = 0; ni < 4; ni++) {
                const int n = wn * 32 + ni * 8 + gid;   // key row
                bf[ni][0] = __float_as_uint(Ks[n * KSTR + kb + tig    ]);
                bf[ni][1] = __float_as_uint(Ks[n * KSTR + kb + tig + 4]);
            }
            #pragma unroll
            for (int mi = 0; mi < 2; mi++)
                #pragma unroll
                for (int ni = 0; ni < 4; ni++)
                    mma_tf32(sacc[mi][ni], qf[mi][kk], bf[ni]);
        }

        // ---- softmax phase 1: per-warp partial row max ----
        #pragma unroll
        for (int mi = 0; mi < 2; mi++) {
            #pragma unroll
            for (int half = 0; half < 2; half++) {
                float px = -1e30f;
                #pragma unroll
                for (int ni = 0; ni < 4; ni++) {
                    px = fmaxf(px, fmaxf(sacc[mi][ni][2 * half],
                                         sacc[mi][ni][2 * half + 1]));
                }
                px = fmaxf(px, __shfl_xor_sync(0xffffffff, px, 1));
                px = fmaxf(px, __shfl_xor_sync(0xffffffff, px, 2));
                if (tig == 0) {
                    const int row = wm * 32 + mi * 16 + half * 8 + gid;
                    Pmx[row * 2 + wn] = px;
                }
            }
        }
        __syncthreads();

        // ---- softmax phase 2: exp in regs, partial sums, O rescale ----
        #pragma unroll
        for (int mi = 0; mi < 2; mi++) {
            #pragma unroll
            for (int half = 0; half < 2; half++) {
                const int idx = mi * 2 + half;
                const int row = wm * 32 + mi * 16 + half * 8 + gid;
                const float mnew = fmaxf(mrun[idx],
                    fmaxf(Pmx[row * 2], Pmx[row * 2 + 1]));
                const float corr = fast_exp(mrun[idx] - mnew);
                mrun[idx] = mnew;
                lrun[idx] *= corr;
                float ps = 0.0f;
                #pragma unroll
                for (int ni = 0; ni < 4; ni++) {
                    float p0 = fast_exp(sacc[mi][ni][2 * half]     - mnew);
                    float p1 = fast_exp(sacc[mi][ni][2 * half + 1] - mnew);
                    sacc[mi][ni][2 * half]     = p0;
                    sacc[mi][ni][2 * half + 1] = p1;
                    ps += p0 + p1;
                    oacc[mi][ni][2 * half]     *= corr;
                    oacc[mi][ni][2 * half + 1] *= corr;
                }
                ps += __shfl_xor_sync(0xffffffff, ps, 1);
                ps += __shfl_xor_sync(0xffffffff, ps, 2);
                if (tig == 0) Psm[row * 2 + wn] = ps;
            }
        }

        // ---- write P (tf32-rounded) to smem for PV A-fragments ----
        #pragma unroll
        for (int mi = 0; mi < 2; mi++) {
            const int m = wm * 32 + mi * 16 + gid;
            #pragma unroll
            for (int ni = 0; ni < 4; ni++) {
                const int n = wn * 32 + ni * 8 + 2 * tig;
                *reinterpret_cast<float2*>(&S[m * SSTR + n]) = make_float2(
                    __int_as_float(f2tf32(sacc[mi][ni][0])),
                    __int_as_float(f2tf32(sacc[mi][ni][1])));
                *reinterpret_cast<float2*>(&S[(m + 8) * SSTR + n]) = make_float2(
                    __int_as_float(f2tf32(sacc[mi][ni][2])),
                    __int_as_float(f2tf32(sacc[mi][ni][3])));
            }
        }
        __syncthreads();

        // ---- finalize l with both warp partials ----
        #pragma unroll
        for (int mi = 0; mi < 2; mi++) {
            #pragma unroll
            for (int half = 0; half < 2; half++) {
                const int idx = mi * 2 + half;
                const int row = wm * 32 + mi * 16 + half * 8 + gid;
                lrun[idx] += Psm[row * 2] + Psm[row * 2 + 1];
            }
        }

        // ---- O += P @ V  (B-frags raw from Vs [s][d], no cvt) ----
        #pragma unroll
        for (int kk = 0; kk < 8; kk++) {
            const int kb = kk * 8;          // s-dim chunk
            uint32_t af[2][4], bf[4][2];
            #pragma unroll
            for (int mi = 0; mi < 2; mi++) {
                const int m = wm * 32 + mi * 16 + gid;
                af[mi][0] = __float_as_uint(S[(m    ) * SSTR + kb + tig    ]);
                af[mi][1] = __float_as_uint(S[(m + 8) * SSTR + kb + tig    ]);
                af[mi][2] = __float_as_uint(S[(m    ) * SSTR + kb + tig + 4]);
                af[mi][3] = __float_as_uint(S[(m + 8) * SSTR + kb + tig + 4]);
            }
            #pragma unroll
            for (int ni = 0; ni < 4; ni++) {
                const int n = wn * 32 + ni * 8 + gid;   // d-col
                bf[ni][0] = __float_as_uint(Vs[(kb + tig    ) * VSTR + n]);
                bf[ni][1] = __float_as_uint(Vs[(kb + tig + 4) * VSTR + n]);
            }
            #pragma unroll
            for (int mi = 0; mi < 2; mi++)
                #pragma unroll
                for (int ni = 0; ni < 4; ni++)
                    mma_tf32(oacc[mi][ni], af[mi], bf[ni]);
        }
        __syncthreads();   // reads of current buffers done before overwrite
        buf ^= 1;
    }

    // ---- epilogue: normalize by l, round to tf32 (proj consumes it) ----
    #pragma unroll
    for (int mi = 0; mi < 2; mi++) {
        const int m = wm * 32 + mi * 16 + gid;
        const float il1 = 1.0f / lrun[mi * 2];
        const float il2 = 1.0f / lrun[mi * 2 + 1];
        #pragma unroll
        for (int ni = 0; ni < 4; ni++) {
            const int n = wn * 32 + ni * 8 + 2 * tig;
            float* y1 = &y[(size_t)(q0 + m) * C_DIM + h * D_DIM + n];
            float* y2 = &y[(size_t)(q0 + m + 8) * C_DIM + h * D_DIM + n];
            *reinterpret_cast<float2*>(y1) = make_float2(
                __int_as_float(f2tf32(oacc[mi][ni][0] * il1)),
                __int_as_float(f2tf32(oacc[mi][ni][1] * il1)));
            *reinterpret_cast<float2*>(y2) = make_float2(
                __int_as_float(f2tf32(oacc[mi][ni][2] * il2)),
                __int_as_float(f2tf32(oacc[mi][ni][3] * il2)));
        }
    }
}

// ---------------------------------------------------------------------------
// kernel_launch
// ---------------------------------------------------------------------------
extern "C" void kernel_launch(void* const* d_in, const int* in_sizes, int n_in,
                              void* d_out, int out_size)
{
    const float* x      = (const float*)d_in[0];
    const float* W_qkv  = (const float*)d_in[1];
    const float* b_qkv  = (const float*)d_in[2];
    const float* W_proj = (const float*)d_in[3];
    const float* b_proj = (const float*)d_in[4];
    float* out = (float*)d_out;

    float *qkv, *y, *xr, *wqr, *wpr;
    cudaGetSymbolAddress((void**)&qkv, g_qkv);
    cudaGetSymbolAddress((void**)&y, g_y);
    cudaGetSymbolAddress((void**)&xr, g_xr);
    cudaGetSymbolAddress((void**)&wqr, g_wqr);
    cudaGetSymbolAddress((void**)&wpr, g_wpr);

    cudaFuncSetAttribute(gemm_tf32_bias,
        cudaFuncAttributeMaxDynamicSharedMemorySize, GEMM_SMEM);
    cudaFuncSetAttribute(attn_tc,
        cudaFuncAttributeMaxDynamicSharedMemorySize, ATTN_SMEM);

    // 0) pre-round inputs to tf32 (hoists every cvt out of the hot loops)
    {
        const int nx = T_DIM * C_DIM / 4;
        const int nq = C_DIM * QKV_N / 4;
        const int np = C_DIM * C_DIM / 4;
        round_tf32_kernel<<<(nx + 255) / 256, 256>>>((const float4*)x,  (float4*)xr,  nx);
        round_tf32_kernel<<<(nq + 255) / 256, 256>>>((const float4*)W_qkv, (float4*)wqr, nq);
        round_tf32_kernel<<<(np + 255) / 256, 256>>>((const float4*)W_proj, (float4*)wpr, np);
    }

    // 1) QKV projection (tf32-rounded output for attention)
    gemm_tf32_bias<<<dim3(QKV_N / GBN, T_DIM / GBM), 256, GEMM_SMEM>>>(
        T_DIM, QKV_N, C_DIM, xr, wqr, b_qkv, qkv, 1);

    // 2) Attention (tf32-rounded y for proj)
    attn_tc<<<dim3(T_DIM / FA_M, H_DIM), 256, ATTN_SMEM>>>(qkv, y);

    // 3) Output projection (fp32 output)
    gemm_tf32_bias<<<dim3(C_DIM / GBN, T_DIM / GBM), 256, GEMM_SMEM>>>(
        T_DIM, C_DIM, C_DIM, y, wpr, b_proj, out, 0);
}

// round 11
// speedup vs baseline: 1.2109x; 1.0917x over previous
#include <cuda_runtime.h>
#include <cuda_bf16.h>
#include <math.h>
#include <stdint.h>

// Problem constants
#define T_DIM 2048
#define C_DIM 1024
#define H_DIM 16
#define D_DIM 64
#define QKV_N (3 * C_DIM)   // 3072

// Scratch (allocation-free: __device__ globals)
__device__ float g_qkv[T_DIM * QKV_N];    // [T, 3C] tf32-rounded qkv
__device__ float g_y[T_DIM * C_DIM];      // [T, C] tf32-rounded attention out
__device__ float g_xr[T_DIM * C_DIM];     // tf32-rounded x
__device__ float g_wqr[C_DIM * QKV_N];    // tf32-rounded W_qkv
__device__ float g_wpr[C_DIM * C_DIM];    // tf32-rounded W_proj

__device__ __forceinline__ uint32_t f2tf32(float x) {
    uint32_t r;
    asm("cvt.rna.tf32.f32 %0, %1;" : "=r"(r) : "f"(x));
    return r;
}

__device__ __forceinline__ void mma_tf32(float* d, const uint32_t* a, const uint32_t* b) {
    asm volatile(
        "mma.sync.aligned.m16n8k8.row.col.f32.tf32.tf32.f32 "
        "{%0,%1,%2,%3}, {%4,%5,%6,%7}, {%8,%9}, {%0,%1,%2,%3};"
        : "+f"(d[0]), "+f"(d[1]), "+f"(d[2]), "+f"(d[3])
        : "r"(a[0]), "r"(a[1]), "r"(a[2]), "r"(a[3]), "r"(b[0]), "r"(b[1]));
}

__device__ __forceinline__ uint32_t smem_u32(const void* p) {
    return (uint32_t)__cvta_generic_to_shared(p);
}
__device__ __forceinline__ void cp_async16(uint32_t dst, const void* src) {
    asm volatile("cp.async.cg.shared.global [%0], [%1], 16;" :: "r"(dst), "l"(src));
}
__device__ __forceinline__ void cp_commit() {
    asm volatile("cp.async.commit_group;");
}
template <int N>
__device__ __forceinline__ void cp_wait() {
    asm volatile("cp.async.wait_group %0;" :: "n"(N));
}

// ---------------------------------------------------------------------------
// Merged elementwise tf32 RNA pre-round for x, W_qkv, W_proj (one launch)
// ---------------------------------------------------------------------------
#define NX4 (T_DIM * C_DIM / 4)     // 524288
#define NQ4 (C_DIM * QKV_N / 4)     // 786432
#define NP4 (C_DIM * C_DIM / 4)     // 262144

__device__ __forceinline__ float4 round4(float4 v) {
    float4 o;
    o.x = __int_as_float(f2tf32(v.x));
    o.y = __int_as_float(f2tf32(v.y));
    o.z = __int_as_float(f2tf32(v.z));
    o.w = __int_as_float(f2tf32(v.w));
    return o;
}

__global__ void round_all_kernel(
    const float4* __restrict__ x, const float4* __restrict__ wq,
    const float4* __restrict__ wp,
    float4* __restrict__ xr, float4* __restrict__ wqr, float4* __restrict__ wpr)
{
    const int i = blockIdx.x * blockDim.x + threadIdx.x;
    if (i < NX4) {
        xr[i] = round4(x[i]);
    } else if (i < NX4 + NQ4) {
        wqr[i - NX4] = round4(wq[i - NX4]);
    } else if (i < NX4 + NQ4 + NP4) {
        wpr[i - NX4 - NQ4] = round4(wp[i - NX4 - NQ4]);
    }
}

// ---------------------------------------------------------------------------
// TF32 tensor-core GEMM, cp.async 3-stage pipeline, zero cvts. (unchanged)
// ---------------------------------------------------------------------------
#define GBM 128
#define GBN 128
#define GBK 32
#define AS_STRIDE 36
#define BS_STRIDE 136
#define AS_WORDS (GBM * AS_STRIDE)            // 4608
#define BS_WORDS (GBK * BS_STRIDE)            // 4352
#define STAGE_WORDS (AS_WORDS + BS_WORDS)     // 8960
#define GSTAGES 3
#define GEMM_SMEM (GSTAGES * STAGE_WORDS * 4) // 107520 B

__global__ __launch_bounds__(256) void gemm_tf32_bias(
    int M, int N, int K,
    const float* __restrict__ A, const float* __restrict__ B,
    const float* __restrict__ bias, float* __restrict__ C, int round_out)
{
    extern __shared__ uint32_t gsm[];

    const int tid  = threadIdx.x;
    const int lane = tid & 31;
    const int warp = tid >> 5;
    const int gid  = lane >> 2;
    const int tig  = lane & 3;

    const int wm = warp & 1;
    const int wn = warp >> 1;

    const int crow = blockIdx.y * GBM;
    const int ccol = blockIdx.x * GBN;

    const int niter = K / GBK;

    auto stage = [&](int s, int k0) {
        uint32_t* As = gsm + s * STAGE_WORDS;
        uint32_t* Bs = As + AS_WORDS;
        #pragma unroll
        for (int p = 0; p < 4; p++) {
            const int idx = tid + p * 256;
            const int ra  = idx >> 3;
            const int ca  = idx & 7;
            cp_async16(smem_u32(&As[ra * AS_STRIDE + ca * 4]),
                       &A[(size_t)(crow + ra) * K + k0 + ca * 4]);
            const int rb  = idx >> 5;
            const int cb  = idx & 31;
            cp_async16(smem_u32(&Bs[rb * BS_STRIDE + cb * 4]),
                       &B[(size_t)(k0 + rb) * N + ccol + cb * 4]);
        }
    };

    float acc[4][4][4];
    #pragma unroll
    for (int i = 0; i < 4; i++)
        #pragma unroll
        for (int j = 0; j < 4; j++)
            #pragma unroll
            for (int r = 0; r < 4; r++) acc[i][j][r] = 0.0f;

    stage(0, 0);       cp_commit();
    stage(1, GBK);     cp_commit();

    for (int i = 0; i < niter; i++) {
        if (i == niter - 1) { cp_wait<0>(); } else { cp_wait<1>(); }
        __syncthreads();

        const uint32_t* As = gsm + (i % GSTAGES) * STAGE_WORDS;
        const uint32_t* Bs = As + AS_WORDS;

        #pragma unroll
        for (int kk = 0; kk < 4; kk++) {
            const int kb = kk * 8;
            uint32_t af[4][4], bf[4][2];
            #pragma unroll
            for (int mi = 0; mi < 4; mi++) {
                const int m = wm * 64 + mi * 16 + gid;
                af[mi][0] = As[(m    ) * AS_STRIDE + kb + tig    ];
                af[mi][1] = As[(m + 8) * AS_STRIDE + kb + tig    ];
                af[mi][2] = As[(m    ) * AS_STRIDE + kb + tig + 4];
                af[mi][3] = As[(m + 8) * AS_STRIDE + kb + tig + 4];
            }
            #pragma unroll
            for (int ni = 0; ni < 4; ni++) {
                const int n = wn * 32 + ni * 8 + gid;
                bf[ni][0] = Bs[(kb + tig    ) * BS_STRIDE + n];
                bf[ni][1] = Bs[(kb + tig + 4) * BS_STRIDE + n];
            }
            #pragma unroll
            for (int mi = 0; mi < 4; mi++)
                #pragma unroll
                for (int ni = 0; ni < 4; ni++)
                    mma_tf32(acc[mi][ni], af[mi], bf[ni]);
        }

        if (i + 2 < niter) {
            stage((i + 2) % GSTAGES, (i + 2) * GBK);
            cp_commit();
        }
    }

    #pragma unroll
    for (int mi = 0; mi < 4; mi++) {
        const int r = crow + wm * 64 + mi * 16 + gid;
        #pragma unroll
        for (int ni = 0; ni < 4; ni++) {
            const int c = ccol + wn * 32 + ni * 8 + 2 * tig;
            const float b0 = bias[c], b1 = bias[c + 1];
            float o0 = acc[mi][ni][0] + b0, o1 = acc[mi][ni][1] + b1;
            float o2 = acc[mi][ni][2] + b0, o3 = acc[mi][ni][3] + b1;
            if (round_out) {
                o0 = __int_as_float(f2tf32(o0));
                o1 = __int_as_float(f2tf32(o1));
                o2 = __int_as_float(f2tf32(o2));
                o3 = __int_as_float(f2tf32(o3));
            }
            *reinterpret_cast<float2*>(&C[(size_t)r * N + c]) =
                make_float2(o0, o1);
            *reinterpret_cast<float2*>(&C[(size_t)(r + 8) * N + c]) =
                make_float2(o2, o3);
        }
    }
}

// ---------------------------------------------------------------------------
// Fast exp on FMA/ALU pipes only. Valid for x <= 0 (clamped). Rel err ~2e-6.
// ---------------------------------------------------------------------------
__device__ __forceinline__ float fast_exp(float x) {
    x = fmaxf(x, -87.3f);
    float z = x * 1.4426950408889634f;
    float t = z + 12582912.0f;
    int   n = __float_as_int(t);
    float fi = t - 12582912.0f;
    float f = z - fi;
    float p =          1.3534543e-3f;
    p = fmaf(p, f,     9.6178720e-3f);
    p = fmaf(p, f,     5.5503429e-2f);
    p = fmaf(p, f,     2.4022651e-1f);
    p = fmaf(p, f,     6.9314718e-1f);
    p = fmaf(p, f,     1.0f);
    int sb = (n << 23) + 0x3F800000;
    return p * __int_as_float(sb);
}

// ---------------------------------------------------------------------------
// Tensor-core flash attention, 2 CTAs/SM.
// 4(m) x 2(n) warps, Q in dedicated smem (A-frags reloaded per k-step ->
// register count fits 128 => 2 CTAs/SM). K/V single-buffered cp.async: the
// staging latency of tile i+1 (issued after the last-read barrier of tile i)
// is hidden by the co-resident CTA. 256 CTAs at 2/SM = one wave.
// ---------------------------------------------------------------------------
#define FA_M 128
#define FA_S 64
#define QSTR 68
#define SSTR 68
#define KSTR 68
#define VSTR 72
#define QS_WORDS (FA_M * QSTR)   // 8704
#define S_WORDS  (FA_M * SSTR)   // 8704
#define KT_WORDS (FA_S * KSTR)   // 4352
#define VT_WORDS (FA_S * VSTR)   // 4608
#define ATTN_SMEM ((QS_WORDS + S_WORDS + KT_WORDS + VT_WORDS + 4 * 128) * 4) // 107520

__global__ __launch_bounds__(256, 2) void attn_tc(
    const float* __restrict__ qkv, float* __restrict__ y)
{
    extern __shared__ float sm[];
    float* QS   = sm;                          // [128][QSTR] Q (persistent)
    float* S    = QS + QS_WORDS;               // [128][SSTR] P tile
    float* Kt   = S + S_WORDS;                 // [64][KSTR]
    float* Vt   = Kt + KT_WORDS;               // [64][VSTR]
    float* Pmx  = Vt + VT_WORDS;               // [128][2]
    float* Psm  = Pmx + 2 * 128;               // [128][2]

    const int h  = blockIdx.y;
    const int q0 = blockIdx.x * FA_M;
    const int tid  = threadIdx.x;
    const int lane = tid & 31;
    const int warp = tid >> 5;
    const int gid  = lane >> 2;
    const int tig  = lane & 3;
    const int wm   = warp & 3;    // 0..3 -> 32 m-rows each
    const int wn   = warp >> 2;   // 0..1 -> 32 n-cols each

    const float* qbase = qkv + h * D_DIM;
    const float* kbase = qkv + C_DIM + h * D_DIM;
    const float* vbase = qkv + 2 * C_DIM + h * D_DIM;

    // ---- prologue: async-stage K/V tile 0; stage Q (pre-rounded, *1/8 exact)
    #pragma unroll
    for (int p = 0; p < 4; p++) {
        const int idx = tid + p * 256;
        const int r  = idx >> 4;
        const int c4 = idx & 15;
        cp_async16(smem_u32(&Kt[r * KSTR + c4 * 4]),
                   &kbase[(size_t)r * QKV_N + c4 * 4]);
        cp_async16(smem_u32(&Vt[r * VSTR + c4 * 4]),
                   &vbase[(size_t)r * QKV_N + c4 * 4]);
    }
    cp_commit();

    for (int i = tid; i < FA_M * 16; i += 256) {
        const int r  = i >> 4;
        const int c4 = i & 15;
        float4 v = *reinterpret_cast<const float4*>(
            &qbase[(size_t)(q0 + r) * QKV_N + c4 * 4]);
        float* dst = &QS[r * QSTR + c4 * 4];
        dst[0] = v.x * 0.125f;
        dst[1] = v.y * 0.125f;
        dst[2] = v.z * 0.125f;
        dst[3] = v.w * 0.125f;
    }

    float oacc[2][4][4];
    #pragma unroll
    for (int mi = 0; mi < 2; mi++)
        #pragma unroll
        for (int ni = 0; ni < 4; ni++)
            #pragma unroll
            for (int r = 0; r < 4; r++) oacc[mi][ni][r] = 0.0f;

    float mrun[4] = {-1e30f, -1e30f, -1e30f, -1e30f};
    float lrun[4] = {0.0f, 0.0f, 0.0f, 0.0f};

    const int m0 = wm * 32 + gid;   // row base for mi=0 (mi=1 -> +16)

    for (int it = 0; it < T_DIM / FA_S; it++) {
        cp_wait<0>();
        __syncthreads();   // tile `it` (and Q on it==0) visible

        // ---- S = Q @ K^T (Q A-frags reloaded from QS per k-step) ----
        float sacc[2][4][4];
        #pragma unroll
        for (int mi = 0; mi < 2; mi++)
            #pragma unroll
            for (int ni = 0; ni < 4; ni++)
                #pragma unroll
                for (int r = 0; r < 4; r++) sacc[mi][ni][r] = 0.0f;

        #pragma unroll
        for (int kk = 0; kk < 8; kk++) {
            const int kb = kk * 8;
            uint32_t af[2][4], bf[4][2];
            #pragma unroll
            for (int mi = 0; mi < 2; mi++) {
                const int m = m0 + mi * 16;
                af[mi][0] = __float_as_uint(QS[(m    ) * QSTR + kb + tig    ]);
                af[mi][1] = __float_as_uint(QS[(m + 8) * QSTR + kb + tig    ]);
                af[mi][2] = __float_as_uint(QS[(m    ) * QSTR + kb + tig + 4]);
                af[mi][3] = __float_as_uint(QS[(m + 8) * QSTR + kb + tig + 4]);
            }
            #pragma unroll
            for (int ni = 0; ni < 4; ni++) {
                const int n = wn * 32 + ni * 8 + gid;   // key row
                bf[ni][0] = __float_as_uint(Kt[n * KSTR + kb + tig    ]);
                bf[ni][1] = __float_as_uint(Kt[n * KSTR + kb + tig + 4]);
            }
            #pragma unroll
            for (int mi = 0; mi < 2; mi++)
                #pragma unroll
                for (int ni = 0; ni < 4; ni++)
                    mma_tf32(sacc[mi][ni], af[mi], bf[ni]);
        }

        // ---- softmax phase 1: per-warp partial row max ----
        #pragma unroll
        for (int mi = 0; mi < 2; mi++) {
            #pragma unroll
            for (int half = 0; half < 2; half++) {
                float px = -1e30f;
                #pragma unroll
                for (int ni = 0; ni < 4; ni++) {
                    px = fmaxf(px, fmaxf(sacc[mi][ni][2 * half],
                                         sacc[mi][ni][2 * half + 1]));
                }
                px = fmaxf(px, __shfl_xor_sync(0xffffffff, px, 1));
                px = fmaxf(px, __shfl_xor_sync(0xffffffff, px, 2));
                if (tig == 0) {
                    const int row = m0 + mi * 16 + half * 8;
                    Pmx[row * 2 + wn] = px;
                }
            }
        }
        __syncthreads();

        // ---- softmax phase 2: exp in regs, partial sums, O rescale ----
        #pragma unroll
        for (int mi = 0; mi < 2; mi++) {
            #pragma unroll
            for (int half = 0; half < 2; half++) {
                const int idx = mi * 2 + half;
                const int row = m0 + mi * 16 + half * 8;
                const float mnew = fmaxf(mrun[idx],
                    fmaxf(Pmx[row * 2], Pmx[row * 2 + 1]));
                const float corr = fast_exp(mrun[idx] - mnew);
                mrun[idx] = mnew;
                lrun[idx] *= corr;
                float ps = 0.0f;
                #pragma unroll
                for (int ni = 0; ni < 4; ni++) {
                    float p0 = fast_exp(sacc[mi][ni][2 * half]     - mnew);
                    float p1 = fast_exp(sacc[mi][ni][2 * half + 1] - mnew);
                    sacc[mi][ni][2 * half]     = p0;
                    sacc[mi][ni][2 * half + 1] = p1;
                    ps += p0 + p1;
                    oacc[mi][ni][2 * half]     *= corr;
                    oacc[mi][ni][2 * half + 1] *= corr;
                }
                ps += __shfl_xor_sync(0xffffffff, ps, 1);
                ps += __shfl_xor_sync(0xffffffff, ps, 2);
                if (tig == 0) Psm[row * 2 + wn] = ps;
            }
        }

        // ---- write P (tf32-rounded) to smem for PV A-fragments ----
        #pragma unroll
        for (int mi = 0; mi < 2; mi++) {
            const int m = m0 + mi * 16;
            #pragma unroll
            for (int ni = 0; ni < 4; ni++) {
                const int n = wn * 32 + ni * 8 + 2 * tig;
                *reinterpret_cast<float2*>(&S[m * SSTR + n]) = make_float2(
                    __int_as_float(f2tf32(sacc[mi][ni][0])),
                    __int_as_float(f2tf32(sacc[mi][ni][1])));
                *reinterpret_cast<float2*>(&S[(m + 8) * SSTR + n]) = make_float2(
                    __int_as_float(f2tf32(sacc[mi][ni][2])),
                    __int_as_float(f2tf32(sacc[mi][ni][3])));
            }
        }
        __syncthreads();

        // ---- finalize l with both warp partials ----
        #pragma unroll
        for (int mi = 0; mi < 2; mi++) {
            #pragma unroll
            for (int half = 0; half < 2; half++) {
                const int idx = mi * 2 + half;
                const int row = m0 + mi * 16 + half * 8;
                lrun[idx] += Psm[row * 2] + Psm[row * 2 + 1];
            }
        }

        // ---- O += P @ V ----
        #pragma unroll
        for (int kk = 0; kk < 8; kk++) {
            const int kb = kk * 8;          // s-dim chunk
            uint32_t af[2][4], bf[4][2];
            #pragma unroll
            for (int mi = 0; mi < 2; mi++) {
                const int m = m0 + mi * 16;
                af[mi][0] = __float_as_uint(S[(m    ) * SSTR + kb + tig    ]);
                af[mi][1] = __float_as_uint(S[(m + 8) * SSTR + kb + tig    ]);
                af[mi][2] = __float_as_uint(S[(m    ) * SSTR + kb + tig + 4]);
                af[mi][3] = __float_as_uint(S[(m + 8) * SSTR + kb + tig + 4]);
            }
            #pragma unroll
            for (int ni = 0; ni < 4; ni++) {
                const int n = wn * 32 + ni * 8 + gid;   // d-col
                bf[ni][0] = __float_as_uint(Vt[(kb + tig    ) * VSTR + n]);
                bf[ni][1] = __float_as_uint(Vt[(kb + tig + 4) * VSTR + n]);
            }
            #pragma unroll
            for (int mi = 0; mi < 2; mi++)
                #pragma unroll
                for (int ni = 0; ni < 4; ni++)
                    mma_tf32(oacc[mi][ni], af[mi], bf[ni]);
        }
        __syncthreads();   // all reads of K/V done before restaging

        // ---- restage K/V for tile it+1 (latency hidden by peer CTA) ----
        if (it + 1 < T_DIM / FA_S) {
            const int s0n = (it + 1) * FA_S;
            #pragma unroll
            for (int p = 0; p < 4; p++) {
                const int idx = tid + p * 256;
                const int r  = idx >> 4;
                const int c4 = idx & 15;
                cp_async16(smem_u32(&Kt[r * KSTR + c4 * 4]),
                           &kbase[(size_t)(s0n + r) * QKV_N + c4 * 4]);
                cp_async16(smem_u32(&Vt[r * VSTR + c4 * 4]),
                           &vbase[(size_t)(s0n + r) * QKV_N + c4 * 4]);
            }
            cp_commit();
        }
    }

    // ---- epilogue: normalize by l, round to tf32 (proj consumes it) ----
    #pragma unroll
    for (int mi = 0; mi < 2; mi++) {
        const int m = m0 + mi * 16;
        const float il1 = 1.0f / lrun[mi * 2];
        const float il2 = 1.0f / lrun[mi * 2 + 1];
        #pragma unroll
        for (int ni = 0; ni < 4; ni++) {
            const int n = wn * 32 + ni * 8 + 2 * tig;
            float* y1 = &y[(size_t)(q0 + m) * C_DIM + h * D_DIM + n];
            float* y2 = &y[(size_t)(q0 + m + 8) * C_DIM + h * D_DIM + n];
            *reinterpret_cast<float2*>(y1) = make_float2(
                __int_as_float(f2tf32(oacc[mi][ni][0] * il1)),
                __int_as_float(f2tf32(oacc[mi][ni][1] * il1)));
            *reinterpret_cast<float2*>(y2) = make_float2(
                __int_as_float(f2tf32(oacc[mi][ni][2] * il2)),
                __int_as_float(f2tf32(oacc[mi][ni][3] * il2)));
        }
    }
}

// ---------------------------------------------------------------------------
// kernel_launch
// ---------------------------------------------------------------------------
extern "C" void kernel_launch(void* const* d_in, const int* in_sizes, int n_in,
                              void* d_out, int out_size)
{
    const float* x      = (const float*)d_in[0];
    const float* W_qkv  = (const float*)d_in[1];
    const float* b_qkv  = (const float*)d_in[2];
    const float* W_proj = (const float*)d_in[3];
    const float* b_proj = (const float*)d_in[4];
    float* out = (float*)d_out;

    float *qkv, *y, *xr, *wqr, *wpr;
    cudaGetSymbolAddress((void**)&qkv, g_qkv);
    cudaGetSymbolAddress((void**)&y, g_y);
    cudaGetSymbolAddress((void**)&xr, g_xr);
    cudaGetSymbolAddress((void**)&wqr, g_wqr);
    cudaGetSymbolAddress((void**)&wpr, g_wpr);

    cudaFuncSetAttribute(gemm_tf32_bias,
        cudaFuncAttributeMaxDynamicSharedMemorySize, GEMM_SMEM);
    cudaFuncSetAttribute(attn_tc,
        cudaFuncAttributeMaxDynamicSharedMemorySize, ATTN_SMEM);

    // 0) single merged pre-round of x, W_qkv, W_proj to tf32
    {
        const int total = NX4 + NQ4 + NP4;
        round_all_kernel<<<(total + 255) / 256, 256>>>(
            (const float4*)x, (const float4*)W_qkv, (const float4*)W_proj,
            (float4*)xr, (float4*)wqr, (float4*)wpr);
    }

    // 1) QKV projection (tf32-rounded output for attention)
    gemm_tf32_bias<<<dim3(QKV_N / GBN, T_DIM / GBM), 256, GEMM_SMEM>>>(
        T_DIM, QKV_N, C_DIM, xr, wqr, b_qkv, qkv, 1);

    // 2) Attention (tf32-rounded y for proj)
    attn_tc<<<dim3(T_DIM / FA_M, H_DIM), 256, ATTN_SMEM>>>(qkv, y);

    // 3) Output projection (fp32 output)
    gemm_tf32_bias<<<dim3(C_DIM / GBN, T_DIM / GBM), 256, GEMM_SMEM>>>(
        T_DIM, C_DIM, C_DIM, y, wpr, b_proj, out, 0);
}